// round 1
// baseline (speedup 1.0000x reference)
#include <cuda_runtime.h>

// StateOuterProductCumsum: S[t,b,d,n] = sum_{s<=t} v[s,b,d]*k[s,b,n]*decay[s,b,n]
// decay[t,b,n] = exp(cumsum_t log(max(alpha,1e-8))) / (exp(total) + 1e-8)
//
// T=1024, B=8, D=64, N=64. Output 134 MB fp32 -> DRAM-write-bound (~17us floor).

#define T_DIM 1024
#define B_DIM 8
#define D_DIM 64
#define N_DIM 64
#define EPS_F 1e-8f

// Scratch: w[t,b,n] = k[t,b,n] * decay[t,b,n]  (2 MB, static device global per rules)
__device__ float g_w[T_DIM * B_DIM * N_DIM];

// One block per (b,n) sequence; blockDim = T. Block-wide inclusive scan of
// log(max(alpha,eps)) over t in shared memory, then emit w = k * exp(cl) / den.
__global__ void decay_kernel(const float* __restrict__ k_in,
                             const float* __restrict__ alpha) {
    const int s = blockIdx.x;            // s = b*N + n  (0..511)
    const int t = threadIdx.x;           // 0..1023
    const int stride = B_DIM * N_DIM;    // 512

    __shared__ float sh[T_DIM];

    float la = logf(fmaxf(alpha[(size_t)t * stride + s], EPS_F));
    sh[t] = la;
    __syncthreads();

    // Hillis-Steele inclusive scan (10 steps)
    #pragma unroll
    for (int off = 1; off < T_DIM; off <<= 1) {
        float add = (t >= off) ? sh[t - off] : 0.0f;
        __syncthreads();
        sh[t] += add;
        __syncthreads();
    }

    float cl    = sh[t];
    float total = sh[T_DIM - 1];
    // Reference: decay = exp(cl) / (exp(total) + 1e-8). total is typically
    // ~-1000 -> exp underflows to 0 -> den = 1e-8, same as reference fp32.
    float inv_den = 1.0f / (expf(total) + EPS_F);

    g_w[(size_t)t * stride + s] =
        k_in[(size_t)t * stride + s] * expf(cl) * inv_den;
}

// One thread per (b,d,n). Sequential cumsum over t.
// Consecutive threads -> consecutive n -> coalesced 128B stores per warp.
// v load is warp-uniform (broadcast); w row is L1-resident across the 4 d's
// a 256-thread block covers.
__global__ void cumsum_kernel(const float* __restrict__ v,
                              float* __restrict__ out) {
    const int g = blockIdx.x * blockDim.x + threadIdx.x;  // 0..32767
    const int b = g >> 12;          // / (D*N)
    const int d = (g >> 6) & 63;
    const int n = g & 63;

    const float* vp = v + b * D_DIM + d;          // + t*512 per step
    const float* wp = g_w + b * N_DIM + n;        // + t*512 per step
    float*       op = out + g;                    // + t*32768 per step

    float acc = 0.0f;
    #pragma unroll 8
    for (int t = 0; t < T_DIM; ++t) {
        acc = fmaf(__ldg(vp + (size_t)t * (B_DIM * D_DIM)),
                   __ldg(wp + (size_t)t * (B_DIM * N_DIM)), acc);
        op[(size_t)t * (B_DIM * D_DIM * N_DIM)] = acc;
    }
}

extern "C" void kernel_launch(void* const* d_in, const int* in_sizes, int n_in,
                              void* d_out, int out_size) {
    const float* v     = (const float*)d_in[0];
    const float* k_in  = (const float*)d_in[1];
    const float* alpha = (const float*)d_in[2];
    float* out = (float*)d_out;

    // Kernel 1: 512 sequences (b,n), block = T threads
    decay_kernel<<<B_DIM * N_DIM, T_DIM>>>(k_in, alpha);

    // Kernel 2: 32768 threads = B*D*N, one per output column
    const int threads = 256;
    const int blocks = (B_DIM * D_DIM * N_DIM) / threads;  // 128
    cumsum_kernel<<<blocks, threads>>>(v, out);
}

// round 2
// speedup vs baseline: 2.3337x; 2.3337x over previous
#include <cuda_runtime.h>

// StateOuterProductCumsum: S[t,b,d,n] = sum_{s<=t} v[s,b,d]*k[s,b,n]*decay[s,b,n]
// decay[t,b,n] = exp(cumsum_t log(max(alpha,1e-8))) / (exp(total) + 1e-8)
// T=1024, B=8, D=64, N=64. Output 134 MB fp32 -> DRAM-write-bound floor ~17us.
//
// Pipeline:
//  1) decay_kernel : w[t,b,n] = k*decay (block scan per (b,n), warp-shfl based)
//  2) partial_kernel: P[c][col] = sum over chunk c of v*w   (C=32 chunks of 32)
//  3) scan_kernel  : g_off[c][col] = exclusive prefix of P over c
//  4) cumsum_kernel: acc = g_off + running sum within chunk, streamed stores

#define T_DIM 1024
#define B_DIM 8
#define D_DIM 64
#define N_DIM 64
#define EPS_F 1e-8f

#define NCHUNK 32
#define CLEN   (T_DIM / NCHUNK)          // 32
#define NCOL   (B_DIM * D_DIM * N_DIM)   // 32768
#define NCOL4  (NCOL / 4)                // 8192

__device__ float g_w  [T_DIM * B_DIM * N_DIM];   // 2 MB
__device__ float4 g_p  [NCHUNK * NCOL4];          // 4 MB
__device__ float4 g_off[NCHUNK * NCOL4];          // 4 MB

// ---------------------------------------------------------------------------
// 1) decay: one block per (b,n); 1024 threads; warp-shfl scan (2 barriers).
__global__ void decay_kernel(const float* __restrict__ k_in,
                             const float* __restrict__ alpha) {
    const int s = blockIdx.x;                 // b*N + n
    const int t = threadIdx.x;                // 0..1023
    const int warp = t >> 5, lane = t & 31;
    const int stride = B_DIM * N_DIM;         // 512

    __shared__ float sh_warp[32];

    float la = logf(fmaxf(alpha[(size_t)t * stride + s], EPS_F));

    // warp inclusive scan
    float x = la;
    #pragma unroll
    for (int off = 1; off < 32; off <<= 1) {
        float y = __shfl_up_sync(0xFFFFFFFFu, x, off);
        if (lane >= off) x += y;
    }
    if (lane == 31) sh_warp[warp] = x;
    __syncthreads();

    // warp 0 scans the 32 warp totals (inclusive)
    if (warp == 0) {
        float ws = sh_warp[lane];
        #pragma unroll
        for (int off = 1; off < 32; off <<= 1) {
            float y = __shfl_up_sync(0xFFFFFFFFu, ws, off);
            if (lane >= off) ws += y;
        }
        sh_warp[lane] = ws;   // now inclusive scan of warp sums
    }
    __syncthreads();

    float cl    = x + ((warp > 0) ? sh_warp[warp - 1] : 0.0f);
    float total = sh_warp[31];
    float inv_den = 1.0f / (expf(total) + EPS_F);

    g_w[(size_t)t * stride + s] =
        k_in[(size_t)t * stride + s] * expf(cl) * inv_den;
}

// ---------------------------------------------------------------------------
// Thread index decode shared by partial/cumsum:
//   idx -> n4 (0..15), d (0..63), b (0..7), c (0..31)
// Consecutive lanes cover consecutive n4 -> warp store = 512B contiguous.

// 2) per-chunk partial sums
__global__ void partial_kernel(const float* __restrict__ v) {
    const int idx = blockIdx.x * blockDim.x + threadIdx.x;
    const int n4 = idx & 15;
    const int d  = (idx >> 4) & 63;
    const int b  = (idx >> 10) & 7;
    const int c  = idx >> 13;

    const float*  vp = v + b * D_DIM + d;
    const float4* wp = (const float4*)(g_w + b * N_DIM) + n4;   // +128 float4/step
    const int t0 = c * CLEN;

    float4 acc = make_float4(0.f, 0.f, 0.f, 0.f);
    #pragma unroll 8
    for (int i = 0; i < CLEN; ++i) {
        const int t = t0 + i;
        float  a  = __ldg(vp + (size_t)t * (B_DIM * D_DIM));
        float4 w4 = __ldg(wp + (size_t)t * (B_DIM * N_DIM / 4));
        acc.x = fmaf(a, w4.x, acc.x);
        acc.y = fmaf(a, w4.y, acc.y);
        acc.z = fmaf(a, w4.z, acc.z);
        acc.w = fmaf(a, w4.w, acc.w);
    }
    const int col4 = (b << 10) + (d << 4) + n4;   // b*1024 + d*16 + n4
    g_p[c * NCOL4 + col4] = acc;
}

// 3) exclusive scan of P over chunks (one thread per col4)
__global__ void scan_kernel() {
    const int col4 = blockIdx.x * blockDim.x + threadIdx.x;
    if (col4 >= NCOL4) return;
    float4 run = make_float4(0.f, 0.f, 0.f, 0.f);
    #pragma unroll
    for (int c = 0; c < NCHUNK; ++c) {
        float4 p = g_p[c * NCOL4 + col4];
        g_off[c * NCOL4 + col4] = run;
        run.x += p.x; run.y += p.y; run.z += p.z; run.w += p.w;
    }
}

// 4) hot kernel: streamed cumsum per chunk
__global__ void cumsum_kernel(const float* __restrict__ v,
                              float* __restrict__ out) {
    const int idx = blockIdx.x * blockDim.x + threadIdx.x;
    const int n4 = idx & 15;
    const int d  = (idx >> 4) & 63;
    const int b  = (idx >> 10) & 7;
    const int c  = idx >> 13;

    const int col4 = (b << 10) + (d << 4) + n4;
    const float*  vp = v + b * D_DIM + d;
    const float4* wp = (const float4*)(g_w + b * N_DIM) + n4;
    float4*       op = (float4*)out + col4;
    const int t0 = c * CLEN;

    float4 acc = g_off[c * NCOL4 + col4];
    #pragma unroll 8
    for (int i = 0; i < CLEN; ++i) {
        const int t = t0 + i;
        float  a  = __ldg(vp + (size_t)t * (B_DIM * D_DIM));
        float4 w4 = __ldg(wp + (size_t)t * (B_DIM * N_DIM / 4));
        acc.x = fmaf(a, w4.x, acc.x);
        acc.y = fmaf(a, w4.y, acc.y);
        acc.z = fmaf(a, w4.z, acc.z);
        acc.w = fmaf(a, w4.w, acc.w);
        __stcs(op + (size_t)t * NCOL4, acc);   // streaming: no reuse of output
    }
}

// ---------------------------------------------------------------------------
extern "C" void kernel_launch(void* const* d_in, const int* in_sizes, int n_in,
                              void* d_out, int out_size) {
    const float* v     = (const float*)d_in[0];
    const float* k_in  = (const float*)d_in[1];
    const float* alpha = (const float*)d_in[2];
    float* out = (float*)d_out;

    decay_kernel<<<B_DIM * N_DIM, T_DIM>>>(k_in, alpha);

    const int threads = 256;
    const int nthreads_chunked = NCHUNK * NCOL4;        // 262144
    partial_kernel<<<nthreads_chunked / threads, threads>>>(v);
    scan_kernel<<<(NCOL4 + threads - 1) / threads, threads>>>();
    cumsum_kernel<<<nthreads_chunked / threads, threads>>>(v, out);
}